// round 9
// baseline (speedup 1.0000x reference)
#include <cuda_runtime.h>
#include <math.h>

// Problem constants: b=2, nc=64, H=W=64
#define Bz 2
#define NC 64
#define Hh 64
#define Ww 64
#define Ls 4096          // H*W
#define KD 576           // nc * 3 * 3
#define EPSF 1e-7f
#define MAXC 24          // fast-path candidate capacity in soft phase
#define CQ   3           // corr candidate chunk per unit
#define RCH  12          // rec candidate chunk
#define GBLK 128         // persistent grid size (<= SM count: co-residency guaranteed)

// Scratch (worst-case cnt == Ls; actual data gives cnt ~ 12 per sample)
__device__ int   g_cnt[Bz];
__device__ int   g_list[Bz][Ls];
__device__ float g_K[Bz][Ls][KD];
__device__ float g_corr[Bz][Ls][Ls];
__device__ float g_sc[Bz][Ls][Ls];
__device__ int   g_bar[6];            // zero-init; reset by last block each run

// ---------------------------------------------------------------------------
// Grid barrier: all GBLK blocks are co-resident (GBLK <= #SMs), so spinning is
// safe. Release: threadfence before arrive. Acquire: threadfence after spin.
// ---------------------------------------------------------------------------
__device__ __forceinline__ void gbar(int slot) {
    __syncthreads();
    if (threadIdx.x == 0) {
        __threadfence();
        atomicAdd(&g_bar[slot], 1);
        while (((volatile int*)g_bar)[slot] < GBLK) __nanosleep(32);
        __threadfence();
    }
    __syncthreads();
}

// 3x3 spatial box-sum of a global corr row (zero outside grid) — slow path
__device__ __forceinline__ float boxsum_g(const float* __restrict__ row, int y, int x) {
    float a = 0.f;
    #pragma unroll
    for (int dy = -1; dy <= 1; dy++) {
        int yy = y + dy;
        if (yy < 0 || yy >= Hh) continue;
        const float* r = row + yy * Ww;
        #pragma unroll
        for (int dx = -1; dx <= 1; dx++) {
            int xx = x + dx;
            if (xx >= 0 && xx < Ww) a += r[xx];
        }
    }
    return a;
}

// ---------------------------------------------------------------------------
// ONE persistent kernel, 5 phases separated by grid barriers.
// ---------------------------------------------------------------------------
__global__ void __launch_bounds__(256) k_fused(const float* __restrict__ fgin,
                                               const float* __restrict__ bgin,
                                               const float* __restrict__ mask,
                                               float* __restrict__ att,
                                               float* __restrict__ flow) {
    int bid = blockIdx.x;
    int tid = threadIdx.x, lane = tid & 31, warp = tid >> 5;   // 8 warps

    __shared__ union {
        struct { float sm[Ls]; } scan;                                        // 16KB
        struct { float red[8]; } build;
        struct { float sfg[32][3][68]; float skc[CQ][KD]; float buf[16][193]; } corr; // 44.5KB
        struct { float raw[MAXC][3][64]; float vsh[MAXC][64]; int sl[MAXC]; } soft;   // 24.1KB
        struct { float sk[RCH][144]; float ssc[RCH][3][72]; float smask[64]; } rec;   // 17.3KB
    } u;
    __shared__ int   wsum[8];
    __shared__ float fred[8];

    // ===== Phase A: scan (blocks 0..Bz-1) =====
    if (bid < Bz) {
        int b = bid;
        #pragma unroll
        for (int k = 0; k < 16; k++)
            u.scan.sm[k * 256 + tid] = mask[b * Ls + k * 256 + tid];
        __syncthreads();

        unsigned okbits = 0; int myc = 0;
        #pragma unroll
        for (int j = 0; j < 16; j++) {
            int l = tid * 16 + j;
            int y = l >> 6, x = l & 63;
            int o = 1;
            #pragma unroll
            for (int dy = -1; dy <= 1; dy++) {
                int yy = y + dy;
                if (yy < 0 || yy >= Hh) continue;
                #pragma unroll
                for (int dx = -1; dx <= 1; dx++) {
                    int xx = x + dx;
                    if (xx >= 0 && xx < Ww && u.scan.sm[yy * Ww + xx] != 0.0f) o = 0;
                }
            }
            okbits |= (unsigned)o << j; myc += o;
        }
        int v = myc;
        #pragma unroll
        for (int off = 1; off < 32; off <<= 1) {
            int t = __shfl_up_sync(0xffffffffu, v, off);
            if (lane >= off) v += t;
        }
        if (lane == 31) wsum[warp] = v;
        __syncthreads();
        if (warp == 0) {
            int t = (lane < 8) ? wsum[lane] : 0;
            #pragma unroll
            for (int off = 1; off < 8; off <<= 1) {
                int q = __shfl_up_sync(0xffffffffu, t, off);
                if (lane >= off) t += q;
            }
            if (lane < 8) wsum[lane] = t;
        }
        __syncthreads();
        int excl = (v - myc) + (warp > 0 ? wsum[warp - 1] : 0);
        #pragma unroll
        for (int j = 0; j < 16; j++)
            if ((okbits >> j) & 1u) g_list[b][excl++] = tid * 16 + j;
        if (tid == 0) g_cnt[b] = wsum[7];
    }
    gbar(0);

    int cnt0 = g_cnt[0], cnt1 = g_cnt[1];

    // ===== Phase B: build normalized kernel rows (one unit per candidate) =====
    for (int uu = bid; uu < cnt0 + cnt1; uu += GBLK) {
        int b = (uu >= cnt0);
        int i = uu - (b ? cnt0 : 0);
        int l = g_list[b][i];
        int y = l >> 6, x = l & 63;
        float pv[3]; float ss = 0.f;
        #pragma unroll
        for (int e3 = 0; e3 < 3; e3++) {
            int e = tid + e3 * 256;
            float v = 0.f;
            if (e < KD) {
                int c = e / 9, pp = e % 9;
                int ph = pp / 3, pw = pp % 3;
                int yy = y + ph - 1, xx = x + pw - 1;
                if (yy >= 0 && yy < Hh && xx >= 0 && xx < Ww)
                    v = bgin[(b * NC + c) * Ls + yy * Ww + xx]
                        * (1.f - mask[b * Ls + yy * Ww + xx]);
                v += EPSF;
            }
            pv[e3] = v; ss += v * v;
        }
        #pragma unroll
        for (int o = 16; o > 0; o >>= 1) ss += __shfl_xor_sync(0xffffffffu, ss, o);
        if (lane == 0) u.build.red[warp] = ss;
        __syncthreads();
        float tot = 0.f;
        #pragma unroll
        for (int w = 0; w < 8; w++) tot += u.build.red[w];
        float inv = 1.f / sqrtf(tot);
        #pragma unroll
        for (int e3 = 0; e3 < 3; e3++) {
            int e = tid + e3 * 256;
            if (e < KD) g_K[b][i][e] = pv[e3] * inv * sqrtf(tot) / sqrtf(tot); // keep div form
        }
        // NOTE: write uses pv/sqrt(tot) exactly:
        #pragma unroll
        for (int e3 = 0; e3 < 3; e3++) { (void)e3; }
        __syncthreads();
    }
    gbar(1);

    // ===== Phase C: corr (512 units: b*256 + y*4 + iq) =====
    for (int uu = bid; uu < Bz * 256; uu += GBLK) {
        int b = uu >> 8, rem = uu & 255;
        int y = rem >> 2, iq = rem & 3;
        int cnt = b ? cnt1 : cnt0;
        int qq = (cnt + 3) >> 2;
        int ibeg = iq * qq, iend = min(ibeg + qq, cnt);
        __syncthreads();
        if (ibeg >= iend) continue;

        int cgi = tid >> 4;
        int xq  = tid & 15;
        int xbase = xq * 4;

        for (int i0 = ibeg; i0 < iend; i0 += CQ) {
            int nch = min(CQ, iend - i0);
            float acc[CQ][4];
            #pragma unroll
            for (int j = 0; j < CQ; j++)
                #pragma unroll
                for (int xo = 0; xo < 4; xo++) acc[j][xo] = 0.f;

            for (int t = tid; t < nch * (KD / 4); t += 256) {
                int i = t / (KD / 4), k = t % (KD / 4);
                ((float4*)u.corr.skc[i])[k] = ((const float4*)&g_K[b][i0 + i][0])[k];
            }

            for (int half = 0; half < 2; half++) {
                for (int t = tid; t < 32 * 3 * 68; t += 256) {
                    int ch = t / 204, rem2 = t % 204;
                    int r = rem2 / 68, j = rem2 % 68;
                    int gy = y - 1 + r;
                    float v = 0.f;
                    if (gy >= 0 && gy < Hh && j >= 1 && j <= 64)
                        v = fgin[(b * NC + half * 32 + ch) * Ls + gy * Ww + (j - 1)];
                    u.corr.sfg[ch][r][j] = v;
                }
                __syncthreads();

                #pragma unroll
                for (int c2 = 0; c2 < 2; c2++) {
                    int ch = cgi * 2 + c2;
                    int cglob = half * 32 + ch;
                    float w[3][6];
                    #pragma unroll
                    for (int r = 0; r < 3; r++) {
                        float4 a = *(const float4*)&u.corr.sfg[ch][r][xbase];
                        float2 e = *(const float2*)&u.corr.sfg[ch][r][xbase + 4];
                        w[r][0] = a.x; w[r][1] = a.y; w[r][2] = a.z; w[r][3] = a.w;
                        w[r][4] = e.x; w[r][5] = e.y;
                    }
                    for (int j = 0; j < nch; j++) {
                        const float* kk = &u.corr.skc[j][cglob * 9];
                        float k0 = kk[0], k1 = kk[1], k2 = kk[2];
                        float k3 = kk[3], k4 = kk[4], k5 = kk[5];
                        float k6 = kk[6], k7 = kk[7], k8 = kk[8];
                        #pragma unroll
                        for (int xo = 0; xo < 4; xo++) {
                            acc[j][xo] += k0 * w[0][xo] + k1 * w[0][xo + 1] + k2 * w[0][xo + 2]
                                        + k3 * w[1][xo] + k4 * w[1][xo + 1] + k5 * w[1][xo + 2]
                                        + k6 * w[2][xo] + k7 * w[2][xo + 1] + k8 * w[2][xo + 2];
                        }
                    }
                }
                __syncthreads();
            }

            for (int j = 0; j < nch; j++)
                #pragma unroll
                for (int xo = 0; xo < 4; xo++)
                    u.corr.buf[cgi][j * 64 + xbase + xo] = acc[j][xo];
            __syncthreads();
            if (tid < nch * 64) {
                float s = 0.f;
                #pragma unroll
                for (int g = 0; g < 16; g++) s += u.corr.buf[g][tid];
                int j = tid >> 6, x = tid & 63;
                g_corr[b][i0 + j][y * Ww + x] = s;
            }
            __syncthreads();
        }
    }
    gbar(2);

    // ===== Phase D: softmax/argmax/flow (128 units: b*64 + y) =====
    for (int uu = bid; uu < Bz * 64; uu += GBLK) {
        int b = uu >> 6, y = uu & 63;
        int cnt = b ? cnt1 : cnt0;
        int gq = tid >> 6, x = tid & 63;
        int s = y * Ww + x;
        __syncthreads();

        if (cnt <= MAXC) {
            for (int i = gq; i < cnt; i += 4) {
                #pragma unroll
                for (int r = 0; r < 3; r++) {
                    int gy = y - 1 + r;
                    u.soft.raw[i][r][x] = (gy >= 0 && gy < Hh) ? g_corr[b][i][gy * Ww + x] : 0.f;
                }
            }
            if (tid < cnt) u.soft.sl[tid] = g_list[b][tid];
            __syncthreads();

            for (int i = gq; i < cnt; i += 4) {
                float a = 0.f;
                #pragma unroll
                for (int r = 0; r < 3; r++) {
                    #pragma unroll
                    for (int dx = -1; dx <= 1; dx++) {
                        int xx = x + dx;
                        if (xx >= 0 && xx < 64) a += u.soft.raw[i][r][xx];
                    }
                }
                u.soft.vsh[i][x] = 10.f * a;
            }
            __syncthreads();

            float vmax = (cnt < Ls) ? 0.f : -INFINITY;
            for (int i = 0; i < cnt; i++) vmax = fmaxf(vmax, u.soft.vsh[i][x]);
            float denom = (cnt < Ls) ? (float)(Ls - cnt) * expf(-vmax) : 0.f;
            float bestv = -INFINITY; int bestl = 0;
            for (int i = 0; i < cnt; i++) {
                float vv = u.soft.vsh[i][x];
                denom += expf(vv - vmax);
                if (vv > bestv) { bestv = vv; bestl = u.soft.sl[i]; }
            }
            float inv = 1.f / denom;
            for (int i = gq; i < cnt; i += 4)
                g_sc[b][i][s] = expf(u.soft.vsh[i][x] - vmax) * inv;

            if (gq == 0) {
                flow[(b * 2 + 0) * Ls + s] = (float)(bestl >> 6) - (float)y;
                flow[(b * 2 + 1) * Ls + s] = (float)(bestl & 63) - (float)x;
            }
            __syncthreads();
        } else {
            if (gq == 0) {
                float vmax = (cnt < Ls) ? 0.f : -INFINITY;
                for (int i = 0; i < cnt; i++) {
                    float vv = 10.f * boxsum_g(&g_corr[b][i][0], y, x);
                    vmax = fmaxf(vmax, vv);
                    g_sc[b][i][s] = vv;
                }
                float denom = (cnt < Ls) ? (float)(Ls - cnt) * expf(-vmax) : 0.f;
                float bestv = -INFINITY; int bestl = 0;
                for (int i = 0; i < cnt; i++) {
                    float vv = g_sc[b][i][s];
                    float e = expf(vv - vmax);
                    denom += e;
                    if (vv > bestv) { bestv = vv; bestl = g_list[b][i]; }
                    g_sc[b][i][s] = e;
                }
                float inv = 1.f / denom;
                for (int i = 0; i < cnt; i++) g_sc[b][i][s] *= inv;
                flow[(b * 2 + 0) * Ls + s] = (float)(bestl >> 6) - (float)y;
                flow[(b * 2 + 1) * Ls + s] = (float)(bestl & 63) - (float)x;
            }
            __syncthreads();
        }
    }
    gbar(3);

    // ===== Phase E: rec (512 units: (b*64+y)*4 + cg) =====
    for (int uu = bid; uu < Bz * 256; uu += GBLK) {
        int b = uu >> 8, rem = uu & 255;
        int y = rem >> 2, cg = rem & 3;
        int cnt = b ? cnt1 : cnt0;
        int c16 = tid >> 4, xg = tid & 15;
        int c = cg * 16 + c16;
        int xbase = xg * 4;
        __syncthreads();

        if (tid < 64) u.rec.smask[tid] = mask[b * Ls + y * Ww + tid];

        float acc[4] = {0.f, 0.f, 0.f, 0.f};

        for (int c0 = 0; c0 < cnt; c0 += RCH) {
            int nchunk = min(RCH, cnt - c0);
            for (int t = tid; t < nchunk * 144; t += 256) {
                int i = t / 144, k = t % 144;
                u.rec.sk[i][k] = g_K[b][c0 + i][cg * 144 + k];
            }
            for (int t = tid; t < nchunk * 216; t += 256) {
                int i = t / 216, rem2 = t % 216;
                int r = rem2 / 72, j = rem2 % 72;
                int gy = y - 1 + r;
                float v = 0.f;
                if (gy >= 0 && gy < Hh && j >= 1 && j <= 64)
                    v = g_sc[b][c0 + i][gy * Ww + (j - 1)];
                u.rec.ssc[i][r][j] = v;
            }
            __syncthreads();

            for (int i = 0; i < nchunk; i++) {
                float ki[9];
                #pragma unroll
                for (int p = 0; p < 9; p++) ki[p] = u.rec.sk[i][c16 * 9 + p];
                #pragma unroll
                for (int ph = 0; ph < 3; ph++) {
                    const float* row = u.rec.ssc[i][2 - ph];
                    float4 a = *(const float4*)&row[xbase];
                    float2 e = *(const float2*)&row[xbase + 4];
                    float w0 = a.x, w1 = a.y, w2 = a.z, w3 = a.w, w4 = e.x, w5 = e.y;
                    acc[0] += ki[ph * 3 + 0] * w2 + ki[ph * 3 + 1] * w1 + ki[ph * 3 + 2] * w0;
                    acc[1] += ki[ph * 3 + 0] * w3 + ki[ph * 3 + 1] * w2 + ki[ph * 3 + 2] * w1;
                    acc[2] += ki[ph * 3 + 0] * w4 + ki[ph * 3 + 1] * w3 + ki[ph * 3 + 2] * w2;
                    acc[3] += ki[ph * 3 + 0] * w5 + ki[ph * 3 + 1] * w4 + ki[ph * 3 + 2] * w3;
                }
            }
            __syncthreads();
        }

        const float* fgrow = fgin + (b * NC + c) * Ls + y * Ww + xbase;
        float4 fgv = *(const float4*)fgrow;
        float4 o;
        {
            float m0 = u.rec.smask[xbase + 0], m1 = u.rec.smask[xbase + 1];
            float m2 = u.rec.smask[xbase + 2], m3 = u.rec.smask[xbase + 3];
            o.x = ((acc[0] * m0) / 9.f) * m0 + fgv.x * (1.f - m0);
            o.y = ((acc[1] * m1) / 9.f) * m1 + fgv.y * (1.f - m1);
            o.z = ((acc[2] * m2) / 9.f) * m2 + fgv.z * (1.f - m2);
            o.w = ((acc[3] * m3) / 9.f) * m3 + fgv.w * (1.f - m3);
        }
        *(float4*)(att + (b * NC + c) * Ls + y * Ww + xbase) = o;
    }

    // ===== Done: last block resets barrier counters for the next replay =====
    __syncthreads();
    if (threadIdx.x == 0) {
        __threadfence();
        if (atomicAdd(&g_bar[5], 1) == GBLK - 1) {
            #pragma unroll
            for (int i = 0; i < 6; i++) g_bar[i] = 0;
            __threadfence();
        }
    }
}

// ---------------------------------------------------------------------------
extern "C" void kernel_launch(void* const* d_in, const int* in_sizes, int n_in,
                              void* d_out, int out_size) {
    const float* fg   = (const float*)d_in[0];   // foreground [2,64,64,64]
    const float* bg   = (const float*)d_in[1];   // background [2,64,64,64]
    const float* mask = (const float*)d_in[2];   // mask       [2,1,64,64]
    float* att  = (float*)d_out;                 // attended   [2,64,64,64]
    float* flow = (float*)d_out + Bz * NC * Ls;  // flow       [2,2,64,64]

    k_fused<<<GBLK, 256>>>(fg, bg, mask, att, flow);
}

// round 10
// speedup vs baseline: 1.2735x; 1.2735x over previous
#include <cuda_runtime.h>
#include <math.h>

// Problem constants: b=2, nc=64, H=W=64
#define Bz 2
#define NC 64
#define Hh 64
#define Ww 64
#define Ls 4096          // H*W
#define KD 576           // nc * 3 * 3
#define EPSF 1e-7f
#define MAXC 24          // fast-path candidate capacity in soft phase
#define CQ   3           // corr candidate chunk per unit
#define RCH  12          // rec candidate chunk
#define GBLK 512         // persistent grid: 4 blocks/SM x 148 SMs = 592 >= 512

// Scratch (worst-case cnt == Ls; actual data gives cnt ~ 12 per sample)
__device__ int   g_cnt[Bz];
__device__ int   g_list[Bz][Ls];
__device__ float g_K[Bz][Ls][KD];
__device__ float g_corr[Bz][Ls][Ls];
__device__ float g_sc[Bz][Ls][Ls];
__device__ int   g_bar[6];            // zero-init; reset by last block each run

// ---------------------------------------------------------------------------
// Grid barrier: all GBLK blocks are co-resident (regs<=64 via launch_bounds,
// smem<=31.6KB, 256 thr => 4 blocks/SM on 148 SMs), so spinning is safe.
// ---------------------------------------------------------------------------
__device__ __forceinline__ void gbar(int slot) {
    __syncthreads();
    if (threadIdx.x == 0) {
        __threadfence();
        atomicAdd(&g_bar[slot], 1);
        while (((volatile int*)g_bar)[slot] < GBLK) __nanosleep(32);
        __threadfence();
    }
    __syncthreads();
}

// 3x3 spatial box-sum of a global corr row (zero outside grid) — slow path
__device__ __forceinline__ float boxsum_g(const float* __restrict__ row, int y, int x) {
    float a = 0.f;
    #pragma unroll
    for (int dy = -1; dy <= 1; dy++) {
        int yy = y + dy;
        if (yy < 0 || yy >= Hh) continue;
        const float* r = row + yy * Ww;
        #pragma unroll
        for (int dx = -1; dx <= 1; dx++) {
            int xx = x + dx;
            if (xx >= 0 && xx < Ww) a += r[xx];
        }
    }
    return a;
}

// ---------------------------------------------------------------------------
// ONE persistent kernel, 5 phases separated by grid barriers.
// ---------------------------------------------------------------------------
__global__ void __launch_bounds__(256, 4) k_fused(const float* __restrict__ fgin,
                                                  const float* __restrict__ bgin,
                                                  const float* __restrict__ mask,
                                                  float* __restrict__ att,
                                                  float* __restrict__ flow) {
    int bid = blockIdx.x;
    int tid = threadIdx.x, lane = tid & 31, warp = tid >> 5;   // 8 warps

    __shared__ union {
        struct { float sm[Ls]; } scan;                                        // 16KB
        struct { float red[8]; } build;
        struct { float sfg[16][3][68]; float skc[CQ][KD]; float buf[16][193]; } corr; // 31.6KB
        struct { float raw[MAXC][3][64]; float vsh[MAXC][64]; int sl[MAXC]; } soft;   // 24.1KB
        struct { float sk[RCH][144]; float ssc[RCH][3][72]; float smask[64]; } rec;   // 17.2KB
    } u;
    __shared__ int wsum[8];

    // ===== Phase A: scan (blocks 0..Bz-1) =====
    if (bid < Bz) {
        int b = bid;
        #pragma unroll
        for (int k = 0; k < 16; k++)
            u.scan.sm[k * 256 + tid] = mask[b * Ls + k * 256 + tid];
        __syncthreads();

        unsigned okbits = 0; int myc = 0;
        #pragma unroll
        for (int j = 0; j < 16; j++) {
            int l = tid * 16 + j;
            int y = l >> 6, x = l & 63;
            int o = 1;
            #pragma unroll
            for (int dy = -1; dy <= 1; dy++) {
                int yy = y + dy;
                if (yy < 0 || yy >= Hh) continue;
                #pragma unroll
                for (int dx = -1; dx <= 1; dx++) {
                    int xx = x + dx;
                    if (xx >= 0 && xx < Ww && u.scan.sm[yy * Ww + xx] != 0.0f) o = 0;
                }
            }
            okbits |= (unsigned)o << j; myc += o;
        }
        int v = myc;
        #pragma unroll
        for (int off = 1; off < 32; off <<= 1) {
            int t = __shfl_up_sync(0xffffffffu, v, off);
            if (lane >= off) v += t;
        }
        if (lane == 31) wsum[warp] = v;
        __syncthreads();
        if (warp == 0) {
            int t = (lane < 8) ? wsum[lane] : 0;
            #pragma unroll
            for (int off = 1; off < 8; off <<= 1) {
                int q = __shfl_up_sync(0xffffffffu, t, off);
                if (lane >= off) t += q;
            }
            if (lane < 8) wsum[lane] = t;
        }
        __syncthreads();
        int excl = (v - myc) + (warp > 0 ? wsum[warp - 1] : 0);
        #pragma unroll
        for (int j = 0; j < 16; j++)
            if ((okbits >> j) & 1u) g_list[b][excl++] = tid * 16 + j;
        if (tid == 0) g_cnt[b] = wsum[7];
    }
    gbar(0);

    int cnt0 = g_cnt[0], cnt1 = g_cnt[1];

    // ===== Phase B: build normalized kernel rows (one unit per candidate) =====
    for (int uu = bid; uu < cnt0 + cnt1; uu += GBLK) {
        int b = (uu >= cnt0);
        int i = uu - (b ? cnt0 : 0);
        int l = g_list[b][i];
        int y = l >> 6, x = l & 63;
        float pv[3]; float ss = 0.f;
        #pragma unroll
        for (int e3 = 0; e3 < 3; e3++) {
            int e = tid + e3 * 256;
            float v = 0.f;
            if (e < KD) {
                int c = e / 9, pp = e % 9;
                int ph = pp / 3, pw = pp % 3;
                int yy = y + ph - 1, xx = x + pw - 1;
                if (yy >= 0 && yy < Hh && xx >= 0 && xx < Ww)
                    v = bgin[(b * NC + c) * Ls + yy * Ww + xx]
                        * (1.f - mask[b * Ls + yy * Ww + xx]);
                v += EPSF;
            }
            pv[e3] = v; ss += v * v;
        }
        #pragma unroll
        for (int o = 16; o > 0; o >>= 1) ss += __shfl_xor_sync(0xffffffffu, ss, o);
        if (lane == 0) u.build.red[warp] = ss;
        __syncthreads();
        float tot = 0.f;
        #pragma unroll
        for (int w = 0; w < 8; w++) tot += u.build.red[w];
        float norm = sqrtf(tot);
        #pragma unroll
        for (int e3 = 0; e3 < 3; e3++) {
            int e = tid + e3 * 256;
            if (e < KD) g_K[b][i][e] = pv[e3] / norm;
        }
        __syncthreads();
    }
    gbar(1);

    // ===== Phase C: corr (512 units: b*256 + y*4 + iq; 1 unit/block) =====
    for (int uu = bid; uu < Bz * 256; uu += GBLK) {
        int b = uu >> 8, rem = uu & 255;
        int y = rem >> 2, iq = rem & 3;
        int cnt = b ? cnt1 : cnt0;
        int qq = (cnt + 3) >> 2;
        int ibeg = iq * qq, iend = min(ibeg + qq, cnt);
        __syncthreads();
        if (ibeg >= iend) continue;

        int cgi = tid >> 4;                  // 0..15: one channel per pass
        int xq  = tid & 15;
        int xbase = xq * 4;

        for (int i0 = ibeg; i0 < iend; i0 += CQ) {
            int nch = min(CQ, iend - i0);
            float acc[CQ][4];
            #pragma unroll
            for (int j = 0; j < CQ; j++)
                #pragma unroll
                for (int xo = 0; xo < 4; xo++) acc[j][xo] = 0.f;

            for (int t = tid; t < nch * (KD / 4); t += 256) {
                int i = t / (KD / 4), k = t % (KD / 4);
                ((float4*)u.corr.skc[i])[k] = ((const float4*)&g_K[b][i0 + i][0])[k];
            }

            for (int qc = 0; qc < 4; qc++) {     // 16 channels per pass
                for (int t = tid; t < 16 * 3 * 68; t += 256) {
                    int ch = t / 204, rem2 = t % 204;
                    int r = rem2 / 68, j = rem2 % 68;
                    int gy = y - 1 + r;
                    float v = 0.f;
                    if (gy >= 0 && gy < Hh && j >= 1 && j <= 64)
                        v = fgin[(b * NC + qc * 16 + ch) * Ls + gy * Ww + (j - 1)];
                    u.corr.sfg[ch][r][j] = v;
                }
                __syncthreads();

                int cglob = qc * 16 + cgi;
                float w[3][6];
                #pragma unroll
                for (int r = 0; r < 3; r++) {
                    float4 a = *(const float4*)&u.corr.sfg[cgi][r][xbase];
                    float2 e = *(const float2*)&u.corr.sfg[cgi][r][xbase + 4];
                    w[r][0] = a.x; w[r][1] = a.y; w[r][2] = a.z; w[r][3] = a.w;
                    w[r][4] = e.x; w[r][5] = e.y;
                }
                for (int j = 0; j < nch; j++) {
                    const float* kk = &u.corr.skc[j][cglob * 9];
                    float k0 = kk[0], k1 = kk[1], k2 = kk[2];
                    float k3 = kk[3], k4 = kk[4], k5 = kk[5];
                    float k6 = kk[6], k7 = kk[7], k8 = kk[8];
                    #pragma unroll
                    for (int xo = 0; xo < 4; xo++) {
                        acc[j][xo] += k0 * w[0][xo] + k1 * w[0][xo + 1] + k2 * w[0][xo + 2]
                                    + k3 * w[1][xo] + k4 * w[1][xo + 1] + k5 * w[1][xo + 2]
                                    + k6 * w[2][xo] + k7 * w[2][xo + 1] + k8 * w[2][xo + 2];
                    }
                }
                __syncthreads();
            }

            for (int j = 0; j < nch; j++)
                #pragma unroll
                for (int xo = 0; xo < 4; xo++)
                    u.corr.buf[cgi][j * 64 + xbase + xo] = acc[j][xo];
            __syncthreads();
            if (tid < nch * 64) {
                float s = 0.f;
                #pragma unroll
                for (int g = 0; g < 16; g++) s += u.corr.buf[g][tid];
                int j = tid >> 6, x = tid & 63;
                g_corr[b][i0 + j][y * Ww + x] = s;
            }
            __syncthreads();
        }
    }
    gbar(2);

    // ===== Phase D: softmax/argmax/flow (128 units: b*64 + y) =====
    for (int uu = bid; uu < Bz * 64; uu += GBLK) {
        int b = uu >> 6, y = uu & 63;
        int cnt = b ? cnt1 : cnt0;
        int gq = tid >> 6, x = tid & 63;
        int s = y * Ww + x;
        __syncthreads();

        if (cnt <= MAXC) {
            for (int i = gq; i < cnt; i += 4) {
                #pragma unroll
                for (int r = 0; r < 3; r++) {
                    int gy = y - 1 + r;
                    u.soft.raw[i][r][x] = (gy >= 0 && gy < Hh) ? g_corr[b][i][gy * Ww + x] : 0.f;
                }
            }
            if (tid < cnt) u.soft.sl[tid] = g_list[b][tid];
            __syncthreads();

            for (int i = gq; i < cnt; i += 4) {
                float a = 0.f;
                #pragma unroll
                for (int r = 0; r < 3; r++) {
                    #pragma unroll
                    for (int dx = -1; dx <= 1; dx++) {
                        int xx = x + dx;
                        if (xx >= 0 && xx < 64) a += u.soft.raw[i][r][xx];
                    }
                }
                u.soft.vsh[i][x] = 10.f * a;
            }
            __syncthreads();

            float vmax = (cnt < Ls) ? 0.f : -INFINITY;
            for (int i = 0; i < cnt; i++) vmax = fmaxf(vmax, u.soft.vsh[i][x]);
            float denom = (cnt < Ls) ? (float)(Ls - cnt) * expf(-vmax) : 0.f;
            float bestv = -INFINITY; int bestl = 0;
            for (int i = 0; i < cnt; i++) {
                float vv = u.soft.vsh[i][x];
                denom += expf(vv - vmax);
                if (vv > bestv) { bestv = vv; bestl = u.soft.sl[i]; }
            }
            float inv = 1.f / denom;
            for (int i = gq; i < cnt; i += 4)
                g_sc[b][i][s] = expf(u.soft.vsh[i][x] - vmax) * inv;

            if (gq == 0) {
                flow[(b * 2 + 0) * Ls + s] = (float)(bestl >> 6) - (float)y;
                flow[(b * 2 + 1) * Ls + s] = (float)(bestl & 63) - (float)x;
            }
            __syncthreads();
        } else {
            if (gq == 0) {
                float vmax = (cnt < Ls) ? 0.f : -INFINITY;
                for (int i = 0; i < cnt; i++) {
                    float vv = 10.f * boxsum_g(&g_corr[b][i][0], y, x);
                    vmax = fmaxf(vmax, vv);
                    g_sc[b][i][s] = vv;
                }
                float denom = (cnt < Ls) ? (float)(Ls - cnt) * expf(-vmax) : 0.f;
                float bestv = -INFINITY; int bestl = 0;
                for (int i = 0; i < cnt; i++) {
                    float vv = g_sc[b][i][s];
                    float e = expf(vv - vmax);
                    denom += e;
                    if (vv > bestv) { bestv = vv; bestl = g_list[b][i]; }
                    g_sc[b][i][s] = e;
                }
                float inv = 1.f / denom;
                for (int i = 0; i < cnt; i++) g_sc[b][i][s] *= inv;
                flow[(b * 2 + 0) * Ls + s] = (float)(bestl >> 6) - (float)y;
                flow[(b * 2 + 1) * Ls + s] = (float)(bestl & 63) - (float)x;
            }
            __syncthreads();
        }
    }
    gbar(3);

    // ===== Phase E: rec (512 units: (b*64+y)*4 + cg; 1 unit/block) =====
    for (int uu = bid; uu < Bz * 256; uu += GBLK) {
        int b = uu >> 8, rem = uu & 255;
        int y = rem >> 2, cg = rem & 3;
        int cnt = b ? cnt1 : cnt0;
        int c16 = tid >> 4, xg = tid & 15;
        int c = cg * 16 + c16;
        int xbase = xg * 4;
        __syncthreads();

        if (tid < 64) u.rec.smask[tid] = mask[b * Ls + y * Ww + tid];
        __syncthreads();

        float acc[4] = {0.f, 0.f, 0.f, 0.f};

        for (int c0 = 0; c0 < cnt; c0 += RCH) {
            int nchunk = min(RCH, cnt - c0);
            for (int t = tid; t < nchunk * 144; t += 256) {
                int i = t / 144, k = t % 144;
                u.rec.sk[i][k] = g_K[b][c0 + i][cg * 144 + k];
            }
            for (int t = tid; t < nchunk * 216; t += 256) {
                int i = t / 216, rem2 = t % 216;
                int r = rem2 / 72, j = rem2 % 72;
                int gy = y - 1 + r;
                float v = 0.f;
                if (gy >= 0 && gy < Hh && j >= 1 && j <= 64)
                    v = g_sc[b][c0 + i][gy * Ww + (j - 1)];
                u.rec.ssc[i][r][j] = v;
            }
            __syncthreads();

            for (int i = 0; i < nchunk; i++) {
                float ki[9];
                #pragma unroll
                for (int p = 0; p < 9; p++) ki[p] = u.rec.sk[i][c16 * 9 + p];
                #pragma unroll
                for (int ph = 0; ph < 3; ph++) {
                    const float* row = u.rec.ssc[i][2 - ph];
                    float4 a = *(const float4*)&row[xbase];
                    float2 e = *(const float2*)&row[xbase + 4];
                    float w0 = a.x, w1 = a.y, w2 = a.z, w3 = a.w, w4 = e.x, w5 = e.y;
                    acc[0] += ki[ph * 3 + 0] * w2 + ki[ph * 3 + 1] * w1 + ki[ph * 3 + 2] * w0;
                    acc[1] += ki[ph * 3 + 0] * w3 + ki[ph * 3 + 1] * w2 + ki[ph * 3 + 2] * w1;
                    acc[2] += ki[ph * 3 + 0] * w4 + ki[ph * 3 + 1] * w3 + ki[ph * 3 + 2] * w2;
                    acc[3] += ki[ph * 3 + 0] * w5 + ki[ph * 3 + 1] * w4 + ki[ph * 3 + 2] * w3;
                }
            }
            __syncthreads();
        }

        const float* fgrow = fgin + (b * NC + c) * Ls + y * Ww + xbase;
        float4 fgv = *(const float4*)fgrow;
        float4 o;
        {
            float m0 = u.rec.smask[xbase + 0], m1 = u.rec.smask[xbase + 1];
            float m2 = u.rec.smask[xbase + 2], m3 = u.rec.smask[xbase + 3];
            o.x = ((acc[0] * m0) / 9.f) * m0 + fgv.x * (1.f - m0);
            o.y = ((acc[1] * m1) / 9.f) * m1 + fgv.y * (1.f - m1);
            o.z = ((acc[2] * m2) / 9.f) * m2 + fgv.z * (1.f - m2);
            o.w = ((acc[3] * m3) / 9.f) * m3 + fgv.w * (1.f - m3);
        }
        *(float4*)(att + (b * NC + c) * Ls + y * Ww + xbase) = o;
    }

    // ===== Done: last block resets barrier counters for the next replay =====
    __syncthreads();
    if (threadIdx.x == 0) {
        __threadfence();
        if (atomicAdd(&g_bar[5], 1) == GBLK - 1) {
            #pragma unroll
            for (int i = 0; i < 6; i++) g_bar[i] = 0;
            __threadfence();
        }
    }
}

// ---------------------------------------------------------------------------
extern "C" void kernel_launch(void* const* d_in, const int* in_sizes, int n_in,
                              void* d_out, int out_size) {
    const float* fg   = (const float*)d_in[0];   // foreground [2,64,64,64]
    const float* bg   = (const float*)d_in[1];   // background [2,64,64,64]
    const float* mask = (const float*)d_in[2];   // mask       [2,1,64,64]
    float* att  = (float*)d_out;                 // attended   [2,64,64,64]
    float* flow = (float*)d_out + Bz * NC * Ls;  // flow       [2,2,64,64]

    k_fused<<<GBLK, 256>>>(fg, bg, mask, att, flow);
}

// round 11
// speedup vs baseline: 1.2741x; 1.0005x over previous
#include <cuda_runtime.h>
#include <math.h>

// Problem constants: b=2, nc=64, H=W=64
#define Bz 2
#define NC 64
#define Hh 64
#define Ww 64
#define Ls 4096          // H*W
#define KD 576           // nc * 3 * 3
#define EPSF 1e-7f
#define MAXC 24          // fast-path candidate capacity in soft phase
#define CQ   3           // corr candidate chunk per unit
#define RCH  12          // rec candidate chunk
#define GBLK 512         // persistent grid: 4 blocks/SM x 148 SMs = 592 >= 512 (proven resident R10)

// Scratch (worst-case cnt == Ls; actual data gives cnt ~ 12 per sample)
__device__ int   g_cnt[Bz];
__device__ int   g_mm[Bz][Ls];
__device__ int   g_list[Bz][Ls];
__device__ float g_K[Bz][Ls][KD];
__device__ float g_corr[Bz][Ls][Ls];
__device__ float g_sc[Bz][Ls][Ls];
__device__ int   g_bar[6];            // slots 0..4 = phase barriers, 5 = done/reset

// ---------------------------------------------------------------------------
// Grid barrier: all GBLK blocks co-resident (64 regs, 31.6KB smem, 256 thr =>
// 4 blocks/SM; non-deadlock proven at GBLK=512 in round 10). nanosleep(256)
// keeps the 500-block poll traffic off the hot L2 slice.
// ---------------------------------------------------------------------------
__device__ __forceinline__ void gbar(int slot) {
    __syncthreads();
    if (threadIdx.x == 0) {
        __threadfence();
        atomicAdd(&g_bar[slot], 1);
        while (((volatile int*)g_bar)[slot] < GBLK) __nanosleep(256);
        __threadfence();
    }
    __syncthreads();
}

// 3x3 spatial box-sum of a global corr row (zero outside grid) — slow path
__device__ __forceinline__ float boxsum_g(const float* __restrict__ row, int y, int x) {
    float a = 0.f;
    #pragma unroll
    for (int dy = -1; dy <= 1; dy++) {
        int yy = y + dy;
        if (yy < 0 || yy >= Hh) continue;
        const float* r = row + yy * Ww;
        #pragma unroll
        for (int dx = -1; dx <= 1; dx++) {
            int xx = x + dx;
            if (xx >= 0 && xx < Ww) a += r[xx];
        }
    }
    return a;
}

// ---------------------------------------------------------------------------
// ONE persistent kernel; phases A1(mm) A2(compact) B(build) C(corr) D(soft)
// E(rec) separated by grid barriers.
// ---------------------------------------------------------------------------
__global__ void __launch_bounds__(256, 4) k_fused(const float* __restrict__ fgin,
                                                  const float* __restrict__ bgin,
                                                  const float* __restrict__ mask,
                                                  float* __restrict__ att,
                                                  float* __restrict__ flow) {
    int bid = blockIdx.x;
    int tid = threadIdx.x, lane = tid & 31, warp = tid >> 5;   // 8 warps

    __shared__ union {
        struct { float sm[Ls]; } scan;                                        // 16KB
        struct { float red[8]; } build;
        struct { float sfg[16][3][68]; float skc[CQ][KD]; float buf[16][193]; } corr; // 31.6KB
        struct { float raw[MAXC][3][64]; float vsh[MAXC][64]; int sl[MAXC]; } soft;   // 24.1KB
        struct { float sk[RCH][144]; float ssc[RCH][3][72]; float smask[64]; } rec;   // 17.2KB
    } u;
    __shared__ int wsum[8];

    // ===== Phase A1: distributed mm flags (1 cell/thread, blocks 0..31) + L2 warm =====
    {
        int gt = bid * 256 + tid;
        if (gt < Bz * Ls) {
            int b = gt >> 12, l = gt & (Ls - 1);
            int y = l >> 6, x = l & 63;
            int o = 1;
            #pragma unroll
            for (int dy = -1; dy <= 1; dy++) {
                int yy = y + dy;
                if (yy < 0 || yy >= Hh) continue;
                #pragma unroll
                for (int dx = -1; dx <= 1; dx++) {
                    int xx = x + dx;
                    if (xx >= 0 && xx < Ww && mask[b * Ls + yy * Ww + xx] != 0.0f) o = 0;
                }
            }
            g_mm[b][l] = o;
        }
        // warm ALL of fg into L2 (512*256 float4 == Bz*NC*Ls floats), overlapped
        float4 wv = ((const float4*)fgin)[bid * 256 + tid];
        if (wv.x == -12345.678f && wv.y == wv.z && wv.z == wv.w) u.scan.sm[0] = wv.w; // never true
    }
    gbar(0);

    // ===== Phase A2: ordered compaction (blocks 0..Bz-1), 16 cells/thread =====
    if (bid < Bz) {
        int b = bid;
        unsigned okbits = 0;
        const int4* mm4 = (const int4*)&g_mm[b][0];
        #pragma unroll
        for (int q = 0; q < 4; q++) {
            int4 f = mm4[tid * 4 + q];
            okbits |= (f.x ? 1u : 0u) << (q * 4 + 0);
            okbits |= (f.y ? 1u : 0u) << (q * 4 + 1);
            okbits |= (f.z ? 1u : 0u) << (q * 4 + 2);
            okbits |= (f.w ? 1u : 0u) << (q * 4 + 3);
        }
        int myc = __popc(okbits);
        int v = myc;
        #pragma unroll
        for (int off = 1; off < 32; off <<= 1) {
            int t = __shfl_up_sync(0xffffffffu, v, off);
            if (lane >= off) v += t;
        }
        if (lane == 31) wsum[warp] = v;
        __syncthreads();
        if (warp == 0) {
            int t = (lane < 8) ? wsum[lane] : 0;
            #pragma unroll
            for (int off = 1; off < 8; off <<= 1) {
                int q = __shfl_up_sync(0xffffffffu, t, off);
                if (lane >= off) t += q;
            }
            if (lane < 8) wsum[lane] = t;
        }
        __syncthreads();
        int excl = (v - myc) + (warp > 0 ? wsum[warp - 1] : 0);
        #pragma unroll
        for (int j = 0; j < 16; j++)
            if ((okbits >> j) & 1u) g_list[b][excl++] = tid * 16 + j;
        if (tid == 0) g_cnt[b] = wsum[7];
    }
    gbar(1);

    int cnt0 = g_cnt[0], cnt1 = g_cnt[1];

    // ===== Phase B: build normalized kernel rows (one unit per candidate) =====
    for (int uu = bid; uu < cnt0 + cnt1; uu += GBLK) {
        int b = (uu >= cnt0);
        int i = uu - (b ? cnt0 : 0);
        int l = g_list[b][i];
        int y = l >> 6, x = l & 63;
        float pv[3]; float ss = 0.f;
        #pragma unroll
        for (int e3 = 0; e3 < 3; e3++) {
            int e = tid + e3 * 256;
            float v = 0.f;
            if (e < KD) {
                int c = e / 9, pp = e % 9;
                int ph = pp / 3, pw = pp % 3;
                int yy = y + ph - 1, xx = x + pw - 1;
                if (yy >= 0 && yy < Hh && xx >= 0 && xx < Ww)
                    v = bgin[(b * NC + c) * Ls + yy * Ww + xx]
                        * (1.f - mask[b * Ls + yy * Ww + xx]);
                v += EPSF;
            }
            pv[e3] = v; ss += v * v;
        }
        #pragma unroll
        for (int o = 16; o > 0; o >>= 1) ss += __shfl_xor_sync(0xffffffffu, ss, o);
        if (lane == 0) u.build.red[warp] = ss;
        __syncthreads();
        float tot = 0.f;
        #pragma unroll
        for (int w = 0; w < 8; w++) tot += u.build.red[w];
        float norm = sqrtf(tot);
        #pragma unroll
        for (int e3 = 0; e3 < 3; e3++) {
            int e = tid + e3 * 256;
            if (e < KD) g_K[b][i][e] = pv[e3] / norm;
        }
        __syncthreads();
    }
    gbar(2);

    // ===== Phase C: corr (512 units: b*256 + y*4 + iq; 1 unit/block) =====
    for (int uu = bid; uu < Bz * 256; uu += GBLK) {
        int b = uu >> 8, rem = uu & 255;
        int y = rem >> 2, iq = rem & 3;
        int cnt = b ? cnt1 : cnt0;
        int qq = (cnt + 3) >> 2;
        int ibeg = iq * qq, iend = min(ibeg + qq, cnt);
        __syncthreads();
        if (ibeg >= iend) continue;

        int cgi = tid >> 4;                  // 0..15: one channel per pass
        int xq  = tid & 15;
        int xbase = xq * 4;

        for (int i0 = ibeg; i0 < iend; i0 += CQ) {
            int nch = min(CQ, iend - i0);
            float acc[CQ][4];
            #pragma unroll
            for (int j = 0; j < CQ; j++)
                #pragma unroll
                for (int xo = 0; xo < 4; xo++) acc[j][xo] = 0.f;

            for (int t = tid; t < nch * (KD / 4); t += 256) {
                int i = t / (KD / 4), k = t % (KD / 4);
                ((float4*)u.corr.skc[i])[k] = ((const float4*)&g_K[b][i0 + i][0])[k];
            }

            for (int qc = 0; qc < 4; qc++) {     // 16 channels per pass
                for (int t = tid; t < 16 * 3 * 68; t += 256) {
                    int ch = t / 204, rem2 = t % 204;
                    int r = rem2 / 68, j = rem2 % 68;
                    int gy = y - 1 + r;
                    float v = 0.f;
                    if (gy >= 0 && gy < Hh && j >= 1 && j <= 64)
                        v = fgin[(b * NC + qc * 16 + ch) * Ls + gy * Ww + (j - 1)];
                    u.corr.sfg[ch][r][j] = v;
                }
                __syncthreads();

                int cglob = qc * 16 + cgi;
                float w[3][6];
                #pragma unroll
                for (int r = 0; r < 3; r++) {
                    float4 a = *(const float4*)&u.corr.sfg[cgi][r][xbase];
                    float2 e = *(const float2*)&u.corr.sfg[cgi][r][xbase + 4];
                    w[r][0] = a.x; w[r][1] = a.y; w[r][2] = a.z; w[r][3] = a.w;
                    w[r][4] = e.x; w[r][5] = e.y;
                }
                for (int j = 0; j < nch; j++) {
                    const float* kk = &u.corr.skc[j][cglob * 9];
                    float k0 = kk[0], k1 = kk[1], k2 = kk[2];
                    float k3 = kk[3], k4 = kk[4], k5 = kk[5];
                    float k6 = kk[6], k7 = kk[7], k8 = kk[8];
                    #pragma unroll
                    for (int xo = 0; xo < 4; xo++) {
                        acc[j][xo] += k0 * w[0][xo] + k1 * w[0][xo + 1] + k2 * w[0][xo + 2]
                                    + k3 * w[1][xo] + k4 * w[1][xo + 1] + k5 * w[1][xo + 2]
                                    + k6 * w[2][xo] + k7 * w[2][xo + 1] + k8 * w[2][xo + 2];
                    }
                }
                __syncthreads();
            }

            for (int j = 0; j < nch; j++)
                #pragma unroll
                for (int xo = 0; xo < 4; xo++)
                    u.corr.buf[cgi][j * 64 + xbase + xo] = acc[j][xo];
            __syncthreads();
            if (tid < nch * 64) {
                float s = 0.f;
                #pragma unroll
                for (int g = 0; g < 16; g++) s += u.corr.buf[g][tid];
                int j = tid >> 6, x = tid & 63;
                g_corr[b][i0 + j][y * Ww + x] = s;
            }
            __syncthreads();
        }
    }
    gbar(3);

    // ===== Phase D: softmax/argmax/flow (128 units: b*64 + y) =====
    for (int uu = bid; uu < Bz * 64; uu += GBLK) {
        int b = uu >> 6, y = uu & 63;
        int cnt = b ? cnt1 : cnt0;
        int gq = tid >> 6, x = tid & 63;
        int s = y * Ww + x;
        __syncthreads();

        if (cnt <= MAXC) {
            for (int i = gq; i < cnt; i += 4) {
                #pragma unroll
                for (int r = 0; r < 3; r++) {
                    int gy = y - 1 + r;
                    u.soft.raw[i][r][x] = (gy >= 0 && gy < Hh) ? g_corr[b][i][gy * Ww + x] : 0.f;
                }
            }
            if (tid < cnt) u.soft.sl[tid] = g_list[b][tid];
            __syncthreads();

            for (int i = gq; i < cnt; i += 4) {
                float a = 0.f;
                #pragma unroll
                for (int r = 0; r < 3; r++) {
                    #pragma unroll
                    for (int dx = -1; dx <= 1; dx++) {
                        int xx = x + dx;
                        if (xx >= 0 && xx < 64) a += u.soft.raw[i][r][xx];
                    }
                }
                u.soft.vsh[i][x] = 10.f * a;
            }
            __syncthreads();

            float vmax = (cnt < Ls) ? 0.f : -INFINITY;
            for (int i = 0; i < cnt; i++) vmax = fmaxf(vmax, u.soft.vsh[i][x]);
            float denom = (cnt < Ls) ? (float)(Ls - cnt) * expf(-vmax) : 0.f;
            float bestv = -INFINITY; int bestl = 0;
            for (int i = 0; i < cnt; i++) {
                float vv = u.soft.vsh[i][x];
                denom += expf(vv - vmax);
                if (vv > bestv) { bestv = vv; bestl = u.soft.sl[i]; }
            }
            float inv = 1.f / denom;
            for (int i = gq; i < cnt; i += 4)
                g_sc[b][i][s] = expf(u.soft.vsh[i][x] - vmax) * inv;

            if (gq == 0) {
                flow[(b * 2 + 0) * Ls + s] = (float)(bestl >> 6) - (float)y;
                flow[(b * 2 + 1) * Ls + s] = (float)(bestl & 63) - (float)x;
            }
            __syncthreads();
        } else {
            if (gq == 0) {
                float vmax = (cnt < Ls) ? 0.f : -INFINITY;
                for (int i = 0; i < cnt; i++) {
                    float vv = 10.f * boxsum_g(&g_corr[b][i][0], y, x);
                    vmax = fmaxf(vmax, vv);
                    g_sc[b][i][s] = vv;
                }
                float denom = (cnt < Ls) ? (float)(Ls - cnt) * expf(-vmax) : 0.f;
                float bestv = -INFINITY; int bestl = 0;
                for (int i = 0; i < cnt; i++) {
                    float vv = g_sc[b][i][s];
                    float e = expf(vv - vmax);
                    denom += e;
                    if (vv > bestv) { bestv = vv; bestl = g_list[b][i]; }
                    g_sc[b][i][s] = e;
                }
                float inv = 1.f / denom;
                for (int i = 0; i < cnt; i++) g_sc[b][i][s] *= inv;
                flow[(b * 2 + 0) * Ls + s] = (float)(bestl >> 6) - (float)y;
                flow[(b * 2 + 1) * Ls + s] = (float)(bestl & 63) - (float)x;
            }
            __syncthreads();
        }
    }
    gbar(4);

    // ===== Phase E: rec (512 units: (b*64+y)*4 + cg; 1 unit/block) =====
    for (int uu = bid; uu < Bz * 256; uu += GBLK) {
        int b = uu >> 8, rem = uu & 255;
        int y = rem >> 2, cg = rem & 3;
        int cnt = b ? cnt1 : cnt0;
        int c16 = tid >> 4, xg = tid & 15;
        int c = cg * 16 + c16;
        int xbase = xg * 4;
        __syncthreads();

        if (tid < 64) u.rec.smask[tid] = mask[b * Ls + y * Ww + tid];
        __syncthreads();

        float acc[4] = {0.f, 0.f, 0.f, 0.f};

        for (int c0 = 0; c0 < cnt; c0 += RCH) {
            int nchunk = min(RCH, cnt - c0);
            for (int t = tid; t < nchunk * 144; t += 256) {
                int i = t / 144, k = t % 144;
                u.rec.sk[i][k] = g_K[b][c0 + i][cg * 144 + k];
            }
            for (int t = tid; t < nchunk * 216; t += 256) {
                int i = t / 216, rem2 = t % 216;
                int r = rem2 / 72, j = rem2 % 72;
                int gy = y - 1 + r;
                float v = 0.f;
                if (gy >= 0 && gy < Hh && j >= 1 && j <= 64)
                    v = g_sc[b][c0 + i][gy * Ww + (j - 1)];
                u.rec.ssc[i][r][j] = v;
            }
            __syncthreads();

            for (int i = 0; i < nchunk; i++) {
                float ki[9];
                #pragma unroll
                for (int p = 0; p < 9; p++) ki[p] = u.rec.sk[i][c16 * 9 + p];
                #pragma unroll
                for (int ph = 0; ph < 3; ph++) {
                    const float* row = u.rec.ssc[i][2 - ph];
                    float4 a = *(const float4*)&row[xbase];
                    float2 e = *(const float2*)&row[xbase + 4];
                    float w0 = a.x, w1 = a.y, w2 = a.z, w3 = a.w, w4 = e.x, w5 = e.y;
                    acc[0] += ki[ph * 3 + 0] * w2 + ki[ph * 3 + 1] * w1 + ki[ph * 3 + 2] * w0;
                    acc[1] += ki[ph * 3 + 0] * w3 + ki[ph * 3 + 1] * w2 + ki[ph * 3 + 2] * w1;
                    acc[2] += ki[ph * 3 + 0] * w4 + ki[ph * 3 + 1] * w3 + ki[ph * 3 + 2] * w2;
                    acc[3] += ki[ph * 3 + 0] * w5 + ki[ph * 3 + 1] * w4 + ki[ph * 3 + 2] * w3;
                }
            }
            __syncthreads();
        }

        const float* fgrow = fgin + (b * NC + c) * Ls + y * Ww + xbase;
        float4 fgv = *(const float4*)fgrow;
        float4 o;
        {
            float m0 = u.rec.smask[xbase + 0], m1 = u.rec.smask[xbase + 1];
            float m2 = u.rec.smask[xbase + 2], m3 = u.rec.smask[xbase + 3];
            o.x = ((acc[0] * m0) / 9.f) * m0 + fgv.x * (1.f - m0);
            o.y = ((acc[1] * m1) / 9.f) * m1 + fgv.y * (1.f - m1);
            o.z = ((acc[2] * m2) / 9.f) * m2 + fgv.z * (1.f - m2);
            o.w = ((acc[3] * m3) / 9.f) * m3 + fgv.w * (1.f - m3);
        }
        *(float4*)(att + (b * NC + c) * Ls + y * Ww + xbase) = o;
    }

    // ===== Done: last block resets barrier counters for the next replay =====
    __syncthreads();
    if (threadIdx.x == 0) {
        __threadfence();
        if (atomicAdd(&g_bar[5], 1) == GBLK - 1) {
            #pragma unroll
            for (int i = 0; i < 6; i++) g_bar[i] = 0;
            __threadfence();
        }
    }
}

// ---------------------------------------------------------------------------
extern "C" void kernel_launch(void* const* d_in, const int* in_sizes, int n_in,
                              void* d_out, int out_size) {
    const float* fg   = (const float*)d_in[0];   // foreground [2,64,64,64]
    const float* bg   = (const float*)d_in[1];   // background [2,64,64,64]
    const float* mask = (const float*)d_in[2];   // mask       [2,1,64,64]
    float* att  = (float*)d_out;                 // attended   [2,64,64,64]
    float* flow = (float*)d_out + Bz * NC * Ls;  // flow       [2,2,64,64]

    k_fused<<<GBLK, 256>>>(fg, bg, mask, att, flow);
}